// round 1
// baseline (speedup 1.0000x reference)
#include <cuda_runtime.h>
#include <cuda_bf16.h>
#include <math.h>

// Problem constants
#define B_     4096
#define NIN    2048
#define NOUT   2048
#define KTOT   (NIN + NOUT)   // 4096
#define NTOT   (4 * NOUT)     // 8192

// GEMM tiling
#define BM  128
#define BN  128
#define BK  16
#define LDA (BM + 4)          // padded smem stride (conflict-free staging)

// 128 MB scratch for gate pre-activations Z[B_, NTOT]
__device__ float g_z[(size_t)B_ * NTOT];

// ---------------------------------------------------------------------------
// Stage a BMxBK tile of T = concat(x, h_old) into smem, transposed to [k][m].
// k0 is a multiple of BK=16, so a float4 never crosses the x/h boundary (2048).
// ---------------------------------------------------------------------------
__device__ __forceinline__ void stage_tile_A(float dst[BK][LDA],
                                             const float* __restrict__ x,
                                             const float* __restrict__ h,
                                             int m0, int k0, int t) {
    int r  = t >> 2;           // 0..63
    int c4 = (t & 3) * 4;      // 0,4,8,12
    int k  = k0 + c4;
    const int from_h = (k >= NIN);
#pragma unroll
    for (int rr = 0; rr < 2; rr++) {
        int m = m0 + r + rr * 64;
        const float* src = from_h ? (h + (size_t)m * NOUT + (k - NIN))
                                  : (x + (size_t)m * NIN + k);
        float4 v = *reinterpret_cast<const float4*>(src);
        dst[c4 + 0][r + rr * 64] = v.x;
        dst[c4 + 1][r + rr * 64] = v.y;
        dst[c4 + 2][r + rr * 64] = v.z;
        dst[c4 + 3][r + rr * 64] = v.w;
    }
}

// Stage a BNxBK tile of W (K-major rows) into smem, transposed to [k][n].
__device__ __forceinline__ void stage_tile_B(float dst[BK][LDA],
                                             const float* __restrict__ W,
                                             int j0, int k0, int t) {
    int r  = t >> 2;
    int c4 = (t & 3) * 4;
    int k  = k0 + c4;
#pragma unroll
    for (int rr = 0; rr < 2; rr++) {
        int j = j0 + r + rr * 64;
        float4 v = *reinterpret_cast<const float4*>(W + (size_t)j * KTOT + k);
        dst[c4 + 0][r + rr * 64] = v.x;
        dst[c4 + 1][r + rr * 64] = v.y;
        dst[c4 + 2][r + rr * 64] = v.z;
        dst[c4 + 3][r + rr * 64] = v.w;
    }
}

// ---------------------------------------------------------------------------
// Z[m, n] = sum_k T[m,k] * W_gate[n%2048, k]    (NT gemm, fp32)
// grid = (NTOT/BN, B_/BM), block = 256 threads, 8x8 microtile per thread.
// ---------------------------------------------------------------------------
__global__ void __launch_bounds__(256, 1)
lstm_gemm_kernel(const float* __restrict__ x,
                 const float* __restrict__ h_old,
                 const float* __restrict__ Wf,
                 const float* __restrict__ Wi,
                 const float* __restrict__ Wo,
                 const float* __restrict__ Wg) {
    __shared__ float As[2][BK][LDA];
    __shared__ float Bs[2][BK][LDA];

    const int m0 = blockIdx.y * BM;
    const int n0 = blockIdx.x * BN;
    const int gate = n0 / NOUT;          // BN=128 divides NOUT=2048, so one gate per block
    const int j0 = n0 % NOUT;
    const float* W = (gate == 0) ? Wf : (gate == 1) ? Wi : (gate == 2) ? Wo : Wg;

    const int t  = threadIdx.x;
    const int tx = t & 15;               // 0..15 -> n microtile
    const int ty = t >> 4;               // 0..15 -> m microtile

    float acc[8][8];
#pragma unroll
    for (int i = 0; i < 8; i++)
#pragma unroll
        for (int j = 0; j < 8; j++) acc[i][j] = 0.0f;

    stage_tile_A(As[0], x, h_old, m0, 0, t);
    stage_tile_B(Bs[0], W, j0, 0, t);
    __syncthreads();

    const int NKB = KTOT / BK;           // 256
    for (int kb = 0; kb < NKB; kb++) {
        int cur = kb & 1;
        if (kb + 1 < NKB) {
            stage_tile_A(As[cur ^ 1], x, h_old, m0, (kb + 1) * BK, t);
            stage_tile_B(Bs[cur ^ 1], W, j0, (kb + 1) * BK, t);
        }
#pragma unroll
        for (int kk = 0; kk < BK; kk++) {
            float a[8], b[8];
            float4 a0 = *reinterpret_cast<const float4*>(&As[cur][kk][ty * 8]);
            float4 a1 = *reinterpret_cast<const float4*>(&As[cur][kk][ty * 8 + 4]);
            float4 b0 = *reinterpret_cast<const float4*>(&Bs[cur][kk][tx * 8]);
            float4 b1 = *reinterpret_cast<const float4*>(&Bs[cur][kk][tx * 8 + 4]);
            a[0]=a0.x; a[1]=a0.y; a[2]=a0.z; a[3]=a0.w;
            a[4]=a1.x; a[5]=a1.y; a[6]=a1.z; a[7]=a1.w;
            b[0]=b0.x; b[1]=b0.y; b[2]=b0.z; b[3]=b0.w;
            b[4]=b1.x; b[5]=b1.y; b[6]=b1.z; b[7]=b1.w;
#pragma unroll
            for (int i = 0; i < 8; i++)
#pragma unroll
                for (int j = 0; j < 8; j++)
                    acc[i][j] = fmaf(a[i], b[j], acc[i][j]);
        }
        __syncthreads();
    }

    // Write back 8x8 per thread, vectorized float4
#pragma unroll
    for (int i = 0; i < 8; i++) {
        size_t row = (size_t)(m0 + ty * 8 + i) * NTOT + (n0 + tx * 8);
        float4 v0 = make_float4(acc[i][0], acc[i][1], acc[i][2], acc[i][3]);
        float4 v1 = make_float4(acc[i][4], acc[i][5], acc[i][6], acc[i][7]);
        *reinterpret_cast<float4*>(&g_z[row])     = v0;
        *reinterpret_cast<float4*>(&g_z[row + 4]) = v1;
    }
}

// ---------------------------------------------------------------------------
// Epilogue: bias + gates + cell update. out = [c (B_*NOUT) | h (B_*NOUT)]
// ---------------------------------------------------------------------------
__device__ __forceinline__ float sigmoidf_(float z) {
    return 1.0f / (1.0f + expf(-z));
}

__global__ void __launch_bounds__(256)
lstm_epilogue_kernel(const float* __restrict__ c_old,
                     const float* __restrict__ bf,
                     const float* __restrict__ bi,
                     const float* __restrict__ bo,
                     const float* __restrict__ bg,
                     float* __restrict__ out) {
    int idx = blockIdx.x * blockDim.x + threadIdx.x;
    if (idx >= B_ * NOUT) return;
    int m = idx / NOUT;
    int j = idx - m * NOUT;
    const float* zrow = g_z + (size_t)m * NTOT;

    float zf = zrow[j]            + bf[j];
    float zi = zrow[NOUT + j]     + bi[j];
    float zo = zrow[2 * NOUT + j] + bo[j];
    float zg = zrow[3 * NOUT + j] + bg[j];

    float f = sigmoidf_(zf);
    float i = sigmoidf_(zi);
    float o = sigmoidf_(zo);
    float g = tanhf(zg);

    float c = f * c_old[idx] + i * g;
    float h = o * tanhf(c);

    out[idx]              = c;
    out[(size_t)B_ * NOUT + idx] = h;
}

// ---------------------------------------------------------------------------
// kernel_launch
// Input order: c_old, h_old, x, Wf, bf, Wi, bi, Wo, bo, Wg, bg, mode
// ---------------------------------------------------------------------------
extern "C" void kernel_launch(void* const* d_in, const int* in_sizes, int n_in,
                              void* d_out, int out_size) {
    const float* c_old = (const float*)d_in[0];
    const float* h_old = (const float*)d_in[1];
    const float* x     = (const float*)d_in[2];
    const float* Wf    = (const float*)d_in[3];
    const float* bf    = (const float*)d_in[4];
    const float* Wi    = (const float*)d_in[5];
    const float* bi    = (const float*)d_in[6];
    const float* Wo    = (const float*)d_in[7];
    const float* bo    = (const float*)d_in[8];
    const float* Wg    = (const float*)d_in[9];
    const float* bg    = (const float*)d_in[10];
    float* out = (float*)d_out;

    dim3 grid(NTOT / BN, B_ / BM);   // (64, 32)
    lstm_gemm_kernel<<<grid, 256>>>(x, h_old, Wf, Wi, Wo, Wg);

    int total = B_ * NOUT;
    lstm_epilogue_kernel<<<(total + 255) / 256, 256>>>(c_old, bf, bi, bo, bg, out);
}

// round 3
// speedup vs baseline: 6.4085x; 6.4085x over previous
#include <cuda_runtime.h>
#include <cuda_fp16.h>
#include <cstdint>
#include <math.h>

// ---------------------------------------------------------------------------
// Problem constants
// ---------------------------------------------------------------------------
#define B_     4096
#define NIN    2048
#define NOUT   2048
#define KTOT   4096              // NIN + NOUT
#define NTOT   8192              // 4 * NOUT

// GEMM tiling
#define BM     128
#define BN     256
#define BK     64
#define STG    3
#define A_STAGE_B  (BM * BK * 2)             // 16384
#define B_STAGE_B  (BN * BK * 2)             // 32768
#define STAGE_B    (A_STAGE_B + B_STAGE_B)   // 49152
#define SMEM_TOTAL (STG * STAGE_B)           // 147456

// ---------------------------------------------------------------------------
// Device scratch (static; no allocation allowed)
// ---------------------------------------------------------------------------
__device__ __align__(16) __half g_Th[(size_t)B_ * KTOT];     // 32 MB
__device__ __align__(16) __half g_Wh[(size_t)NTOT * KTOT];   // 64 MB
__device__ __align__(16) float  g_z[(size_t)B_ * NTOT];      // 128 MB

// ---------------------------------------------------------------------------
// Helpers
// ---------------------------------------------------------------------------
__device__ __forceinline__ uint32_t smem_u32(const void* p) {
    uint32_t a;
    asm("{ .reg .u64 t; cvta.to.shared.u64 t, %1; cvt.u32.u64 %0, t; }" : "=r"(a) : "l"(p));
    return a;
}

__device__ __forceinline__ uint32_t swz(uint32_t off) {
    // 128B-row swizzle: XOR (row%8) into the 16B-chunk index
    return off ^ ((off >> 3) & 0x70);
}

__device__ __forceinline__ void cp16(uint32_t dst, const void* src) {
    asm volatile("cp.async.cg.shared.global [%0], [%1], 16;" :: "r"(dst), "l"(src));
}

__device__ __forceinline__ void ldsm4(uint32_t& d0, uint32_t& d1, uint32_t& d2, uint32_t& d3,
                                      uint32_t addr) {
    asm volatile("ldmatrix.sync.aligned.m8n8.x4.shared.b16 {%0,%1,%2,%3}, [%4];"
                 : "=r"(d0), "=r"(d1), "=r"(d2), "=r"(d3) : "r"(addr));
}

__device__ __forceinline__ void mma16816(float* c,
                                         uint32_t a0, uint32_t a1, uint32_t a2, uint32_t a3,
                                         uint32_t b0, uint32_t b1) {
    asm volatile("mma.sync.aligned.m16n8k16.row.col.f32.f16.f16.f32 "
                 "{%0,%1,%2,%3}, {%4,%5,%6,%7}, {%8,%9}, {%0,%1,%2,%3};"
                 : "+f"(c[0]), "+f"(c[1]), "+f"(c[2]), "+f"(c[3])
                 : "r"(a0), "r"(a1), "r"(a2), "r"(a3), "r"(b0), "r"(b1));
}

// ---------------------------------------------------------------------------
// Conversion kernels: fp32 -> fp16, row-major K-contiguous
// ---------------------------------------------------------------------------
__device__ __forceinline__ uint4 pack8_h(const float* src) {
    float4 v0 = *reinterpret_cast<const float4*>(src);
    float4 v1 = *reinterpret_cast<const float4*>(src + 4);
    __half2 p0 = __floats2half2_rn(v0.x, v0.y);
    __half2 p1 = __floats2half2_rn(v0.z, v0.w);
    __half2 p2 = __floats2half2_rn(v1.x, v1.y);
    __half2 p3 = __floats2half2_rn(v1.z, v1.w);
    uint4 o;
    o.x = *reinterpret_cast<uint32_t*>(&p0);
    o.y = *reinterpret_cast<uint32_t*>(&p1);
    o.z = *reinterpret_cast<uint32_t*>(&p2);
    o.w = *reinterpret_cast<uint32_t*>(&p3);
    return o;
}

__global__ void __launch_bounds__(256)
conv_T_kernel(const float* __restrict__ x, const float* __restrict__ h) {
    uint32_t idx = blockIdx.x * 256 + threadIdx.x;   // B_ * 512
    uint32_t m = idx >> 9;
    uint32_t k = (idx & 511) * 8;
    const float* src = (k < NIN) ? (x + (size_t)m * NIN + k)
                                 : (h + (size_t)m * NOUT + (k - NIN));
    *reinterpret_cast<uint4*>(g_Th + (size_t)m * KTOT + k) = pack8_h(src);
}

__global__ void __launch_bounds__(256)
conv_W_kernel(const float* __restrict__ Wf, const float* __restrict__ Wi,
              const float* __restrict__ Wo, const float* __restrict__ Wg) {
    uint32_t idx = blockIdx.x * 256 + threadIdx.x;   // NTOT * 512
    uint32_t j = idx >> 9;                            // 0..8191
    uint32_t k = (idx & 511) * 8;
    uint32_t gate = j >> 11;
    uint32_t r = j & 2047;
    const float* W = (gate == 0) ? Wf : (gate == 1) ? Wi : (gate == 2) ? Wo : Wg;
    *reinterpret_cast<uint4*>(g_Wh + (size_t)j * KTOT + k) =
        pack8_h(W + (size_t)r * KTOT + k);
}

// ---------------------------------------------------------------------------
// GEMM: g_z[m,n] = sum_k Th[m,k] * Wh[n,k]
// grid = 1024 CTAs (mt = bid&31, nt = bid>>5), 256 threads, 3-stage cp.async.
// ---------------------------------------------------------------------------
__device__ __forceinline__ void stage_slab(uint32_t sA, uint32_t sB,
                                           const __half* __restrict__ gA,
                                           const __half* __restrict__ gB,
                                           int k0, int t) {
    int r     = t >> 2;        // 0..63
    int cbase = t & 3;         // 0..3
#pragma unroll
    for (int rr = 0; rr < 2; rr++) {               // A: 128 rows
        int row = r + rr * 64;
        const __half* src = gA + (size_t)row * KTOT + k0;
#pragma unroll
        for (int i = 0; i < 2; i++) {
            int c16 = cbase + i * 4;               // 16B chunk within 128B row
            uint32_t off = row * 128 + c16 * 16;
            cp16(sA + swz(off), src + c16 * 8);
        }
    }
#pragma unroll
    for (int rr = 0; rr < 4; rr++) {               // B: 256 rows
        int row = r + rr * 64;
        const __half* src = gB + (size_t)row * KTOT + k0;
#pragma unroll
        for (int i = 0; i < 2; i++) {
            int c16 = cbase + i * 4;
            uint32_t off = row * 128 + c16 * 16;
            cp16(sB + swz(off), src + c16 * 8);
        }
    }
}

__global__ void __launch_bounds__(256, 1)
lstm_gemm_kernel() {
    extern __shared__ __align__(1024) char smem[];
    const uint32_t sbase = smem_u32(smem);

    const int t    = threadIdx.x;
    const int lane = t & 31;
    const int wid  = t >> 5;
    const int wm   = wid & 3;      // warp row tile: 32 rows
    const int wn   = wid >> 2;     // warp col tile: 128 cols

    const int bid = blockIdx.x;
    const int mt = bid & 31;
    const int nt = bid >> 5;
    const int m0 = mt * BM;
    const int n0 = nt * BN;

    const __half* gA = g_Th + (size_t)m0 * KTOT;
    const __half* gB = g_Wh + (size_t)n0 * KTOT;

    float acc[2][16][4];
#pragma unroll
    for (int i = 0; i < 2; i++)
#pragma unroll
        for (int j = 0; j < 16; j++)
#pragma unroll
            for (int q = 0; q < 4; q++) acc[i][j][q] = 0.0f;

    // prologue: 2 stages in flight
    stage_slab(sbase, sbase + A_STAGE_B, gA, gB, 0, t);
    asm volatile("cp.async.commit_group;" ::: "memory");
    stage_slab(sbase + STAGE_B, sbase + STAGE_B + A_STAGE_B, gA, gB, BK, t);
    asm volatile("cp.async.commit_group;" ::: "memory");

    const int lrow = lane & 15;
    const int lkof = (lane & 16) ? 8 : 0;

    const int NIT = KTOT / BK;     // 64
    for (int it = 0; it < NIT; it++) {
        asm volatile("cp.async.wait_group 1;" ::: "memory");
        __syncthreads();

        if (it + 2 < NIT) {
            int sn = (it + 2) % STG;
            stage_slab(sbase + sn * STAGE_B, sbase + sn * STAGE_B + A_STAGE_B,
                       gA, gB, (it + 2) * BK, t);
            asm volatile("cp.async.commit_group;" ::: "memory");
        }

        const int s = it % STG;
        const uint32_t aA = sbase + s * STAGE_B;
        const uint32_t aB = aA + A_STAGE_B;

#pragma unroll
        for (int kk = 0; kk < 4; kk++) {
            uint32_t a[2][4];
#pragma unroll
            for (int mf = 0; mf < 2; mf++) {
                uint32_t off = (uint32_t)(wm * 32 + mf * 16 + lrow) * 128
                             + (uint32_t)(kk * 16 + lkof) * 2;
                ldsm4(a[mf][0], a[mf][1], a[mf][2], a[mf][3], aA + swz(off));
            }
#pragma unroll
            for (int nf = 0; nf < 8; nf++) {
                uint32_t off = (uint32_t)(wn * 128 + nf * 16 + lrow) * 128
                             + (uint32_t)(kk * 16 + lkof) * 2;
                uint32_t b0, b1, b2, b3;
                ldsm4(b0, b1, b2, b3, aB + swz(off));
                mma16816(acc[0][nf * 2],     a[0][0], a[0][1], a[0][2], a[0][3], b0, b2);
                mma16816(acc[0][nf * 2 + 1], a[0][0], a[0][1], a[0][2], a[0][3], b1, b3);
                mma16816(acc[1][nf * 2],     a[1][0], a[1][1], a[1][2], a[1][3], b0, b2);
                mma16816(acc[1][nf * 2 + 1], a[1][0], a[1][1], a[1][2], a[1][3], b1, b3);
            }
        }
    }

    // writeback: lane holds rows {r, r+8}, cols 2*(lane%4)+{0,1} per (mf, n8)
    const int mrow = m0 + wm * 32 + (lane >> 2);
    const int ncol = n0 + wn * 128 + (lane & 3) * 2;
#pragma unroll
    for (int mf = 0; mf < 2; mf++) {
#pragma unroll
        for (int n8 = 0; n8 < 16; n8++) {
            float* d0 = g_z + (size_t)(mrow + mf * 16) * NTOT + ncol + n8 * 8;
            float* d1 = g_z + (size_t)(mrow + mf * 16 + 8) * NTOT + ncol + n8 * 8;
            *reinterpret_cast<float2*>(d0) = make_float2(acc[mf][n8][0], acc[mf][n8][1]);
            *reinterpret_cast<float2*>(d1) = make_float2(acc[mf][n8][2], acc[mf][n8][3]);
        }
    }
}

// ---------------------------------------------------------------------------
// Epilogue: bias + gates + cell update, vectorized x4.
// out = [c (B_*NOUT) | h (B_*NOUT)]
// ---------------------------------------------------------------------------
__device__ __forceinline__ float sigmoidf_(float z) { return 1.0f / (1.0f + expf(-z)); }

__global__ void __launch_bounds__(256)
lstm_epilogue_kernel(const float* __restrict__ c_old,
                     const float* __restrict__ bf,
                     const float* __restrict__ bi,
                     const float* __restrict__ bo,
                     const float* __restrict__ bg,
                     float* __restrict__ out) {
    int v = blockIdx.x * blockDim.x + threadIdx.x;
    if (v >= (B_ * NOUT) / 4) return;
    int idx = v * 4;
    int m = idx >> 11;
    int j = idx & 2047;
    const float* zrow = g_z + (size_t)m * NTOT;

    float4 zf = *reinterpret_cast<const float4*>(zrow + j);
    float4 zi = *reinterpret_cast<const float4*>(zrow + NOUT + j);
    float4 zo = *reinterpret_cast<const float4*>(zrow + 2 * NOUT + j);
    float4 zg = *reinterpret_cast<const float4*>(zrow + 3 * NOUT + j);
    float4 bfv = *reinterpret_cast<const float4*>(bf + j);
    float4 biv = *reinterpret_cast<const float4*>(bi + j);
    float4 bov = *reinterpret_cast<const float4*>(bo + j);
    float4 bgv = *reinterpret_cast<const float4*>(bg + j);
    float4 cov = *reinterpret_cast<const float4*>(c_old + idx);

    float zfa[4] = {zf.x + bfv.x, zf.y + bfv.y, zf.z + bfv.z, zf.w + bfv.w};
    float zia[4] = {zi.x + biv.x, zi.y + biv.y, zi.z + biv.z, zi.w + biv.w};
    float zoa[4] = {zo.x + bov.x, zo.y + bov.y, zo.z + bov.z, zo.w + bov.w};
    float zga[4] = {zg.x + bgv.x, zg.y + bgv.y, zg.z + bgv.z, zg.w + bgv.w};
    float co[4]  = {cov.x, cov.y, cov.z, cov.w};
    float c[4], hh[4];
#pragma unroll
    for (int q = 0; q < 4; q++) {
        float f = sigmoidf_(zfa[q]);
        float i = sigmoidf_(zia[q]);
        float o = sigmoidf_(zoa[q]);
        float g = tanhf(zga[q]);
        c[q]  = f * co[q] + i * g;
        hh[q] = o * tanhf(c[q]);
    }
    *reinterpret_cast<float4*>(out + idx) = make_float4(c[0], c[1], c[2], c[3]);
    *reinterpret_cast<float4*>(out + (size_t)B_ * NOUT + idx) =
        make_float4(hh[0], hh[1], hh[2], hh[3]);
}

// ---------------------------------------------------------------------------
// kernel_launch
// Input order: c_old, h_old, x, Wf, bf, Wi, bi, Wo, bo, Wg, bg, mode
// ---------------------------------------------------------------------------
extern "C" void kernel_launch(void* const* d_in, const int* in_sizes, int n_in,
                              void* d_out, int out_size) {
    const float* c_old = (const float*)d_in[0];
    const float* h_old = (const float*)d_in[1];
    const float* x     = (const float*)d_in[2];
    const float* Wf    = (const float*)d_in[3];
    const float* bf    = (const float*)d_in[4];
    const float* Wi    = (const float*)d_in[5];
    const float* bi    = (const float*)d_in[6];
    const float* Wo    = (const float*)d_in[7];
    const float* bo    = (const float*)d_in[8];
    const float* Wg    = (const float*)d_in[9];
    const float* bg    = (const float*)d_in[10];
    float* out = (float*)d_out;

    static int configured = 0;
    if (!configured) {
        cudaFuncSetAttribute(lstm_gemm_kernel,
                             cudaFuncAttributeMaxDynamicSharedMemorySize, SMEM_TOTAL);
        configured = 1;
    }

    conv_T_kernel<<<(B_ * 512) / 256, 256>>>(x, h_old);
    conv_W_kernel<<<(NTOT * 512) / 256, 256>>>(Wf, Wi, Wo, Wg);

    lstm_gemm_kernel<<<(B_ / BM) * (NTOT / BN), 256, SMEM_TOTAL>>>();

    lstm_epilogue_kernel<<<(B_ * NOUT / 4 + 255) / 256, 256>>>(c_old, bf, bi, bo, bg, out);
}

// round 5
// speedup vs baseline: 6.8447x; 1.0681x over previous
#include <cuda_runtime.h>
#include <cuda_fp16.h>
#include <cstdint>
#include <math.h>

// ---------------------------------------------------------------------------
// Problem constants
// ---------------------------------------------------------------------------
#define B_     4096
#define NIN    2048
#define NOUT   2048
#define KTOT   4096              // NIN + NOUT
#define NTOT   8192              // 4 * NOUT

// GEMM tiling: 256(M) x 128(N-packed) x 64(K), 512 threads, 16 warps (4x4)
#define BM     256
#define BN     128
#define BK     64
#define STG    3
#define A_STAGE_B  (BM * BK * 2)             // 32768
#define B_STAGE_B  (BN * BK * 2)             // 16384
#define STAGE_B    (A_STAGE_B + B_STAGE_B)   // 49152
#define SMEM_TOTAL (STG * STAGE_B)           // 147456
#define EPI_PITCH  136                        // fp32 words per row (128 + 8 pad)

// ---------------------------------------------------------------------------
// Device scratch (static; no allocation allowed)
// ---------------------------------------------------------------------------
__device__ __align__(16) __half g_Th[(size_t)B_ * KTOT];     // 32 MB
__device__ __align__(16) __half g_Wh[(size_t)NTOT * KTOT];   // 64 MB (rows: j*4+gate)

// ---------------------------------------------------------------------------
// Helpers
// ---------------------------------------------------------------------------
__device__ __forceinline__ uint32_t smem_u32(const void* p) {
    uint32_t a;
    asm("{ .reg .u64 t; cvta.to.shared.u64 t, %1; cvt.u32.u64 %0, t; }" : "=r"(a) : "l"(p));
    return a;
}

__device__ __forceinline__ uint32_t swz(uint32_t off) {
    return off ^ ((off >> 3) & 0x70);     // 128B-row swizzle
}

__device__ __forceinline__ void cp16(uint32_t dst, const void* src) {
    asm volatile("cp.async.cg.shared.global [%0], [%1], 16;" :: "r"(dst), "l"(src));
}

__device__ __forceinline__ void ldsm4(uint32_t& d0, uint32_t& d1, uint32_t& d2, uint32_t& d3,
                                      uint32_t addr) {
    asm volatile("ldmatrix.sync.aligned.m8n8.x4.shared.b16 {%0,%1,%2,%3}, [%4];"
                 : "=r"(d0), "=r"(d1), "=r"(d2), "=r"(d3) : "r"(addr));
}

__device__ __forceinline__ void mma16816(float* c,
                                         uint32_t a0, uint32_t a1, uint32_t a2, uint32_t a3,
                                         uint32_t b0, uint32_t b1) {
    asm volatile("mma.sync.aligned.m16n8k16.row.col.f32.f16.f16.f32 "
                 "{%0,%1,%2,%3}, {%4,%5,%6,%7}, {%8,%9}, {%0,%1,%2,%3};"
                 : "+f"(c[0]), "+f"(c[1]), "+f"(c[2]), "+f"(c[3])
                 : "r"(a0), "r"(a1), "r"(a2), "r"(a3), "r"(b0), "r"(b1));
}

__device__ __forceinline__ float sigmoidf_(float z) { return 1.0f / (1.0f + expf(-z)); }

// ---------------------------------------------------------------------------
// Conversion kernels: fp32 -> fp16
// ---------------------------------------------------------------------------
__device__ __forceinline__ uint4 pack8_h(const float* src) {
    float4 v0 = *reinterpret_cast<const float4*>(src);
    float4 v1 = *reinterpret_cast<const float4*>(src + 4);
    __half2 p0 = __floats2half2_rn(v0.x, v0.y);
    __half2 p1 = __floats2half2_rn(v0.z, v0.w);
    __half2 p2 = __floats2half2_rn(v1.x, v1.y);
    __half2 p3 = __floats2half2_rn(v1.z, v1.w);
    uint4 o;
    o.x = *reinterpret_cast<uint32_t*>(&p0);
    o.y = *reinterpret_cast<uint32_t*>(&p1);
    o.z = *reinterpret_cast<uint32_t*>(&p2);
    o.w = *reinterpret_cast<uint32_t*>(&p3);
    return o;
}

__global__ void __launch_bounds__(256)
conv_T_kernel(const float* __restrict__ x, const float* __restrict__ h) {
    uint32_t idx = blockIdx.x * 256 + threadIdx.x;   // B_ * 512 threads
    uint32_t m = idx >> 9;
    uint32_t k = (idx & 511) * 8;
    const float* src = (k < NIN) ? (x + (size_t)m * NIN + k)
                                 : (h + (size_t)m * NOUT + (k - NIN));
    *reinterpret_cast<uint4*>(g_Th + (size_t)m * KTOT + k) = pack8_h(src);
}

// Packed W rows: p = j*4 + gate, so a 128-row band = 32 j's x 4 gates.
__global__ void __launch_bounds__(256)
conv_W_kernel(const float* __restrict__ Wf, const float* __restrict__ Wi,
              const float* __restrict__ Wo, const float* __restrict__ Wg) {
    uint32_t idx = blockIdx.x * 256 + threadIdx.x;   // NTOT * 512 threads
    uint32_t jall = idx >> 9;                         // 0..8191 (gate*2048 + j)
    uint32_t k = (idx & 511) * 8;
    uint32_t gate = jall >> 11;
    uint32_t j = jall & 2047;
    const float* W = (gate == 0) ? Wf : (gate == 1) ? Wi : (gate == 2) ? Wo : Wg;
    uint32_t p = j * 4 + gate;
    *reinterpret_cast<uint4*>(g_Wh + (size_t)p * KTOT + k) =
        pack8_h(W + (size_t)j * KTOT + k);
}

// ---------------------------------------------------------------------------
// Fused GEMM + LSTM epilogue.
// grid = 1024 (mt = bid&15, nt = bid>>4), 512 threads, 3-stage cp.async.
// CTA computes Z[m0:m0+256, p0:p0+128] (packed cols = 32 j x 4 gates),
// then applies gates and writes c/h directly.
// ---------------------------------------------------------------------------
__device__ __forceinline__ void stage_slab(uint32_t sA, uint32_t sB,
                                           const __half* __restrict__ gA,
                                           const __half* __restrict__ gB,
                                           int k0, int t) {
    // A: 256 rows x 8 chunks of 16B = 2048 chunks -> 4 per thread
#pragma unroll
    for (int i = 0; i < 4; i++) {
        int c = t + i * 512;
        int row = c >> 3, c16 = c & 7;
        uint32_t off = row * 128 + c16 * 16;
        cp16(sA + swz(off), gA + (size_t)row * KTOT + k0 + c16 * 8);
    }
    // B: 128 rows x 8 chunks = 1024 chunks -> 2 per thread
#pragma unroll
    for (int i = 0; i < 2; i++) {
        int c = t + i * 512;
        int row = c >> 3, c16 = c & 7;
        uint32_t off = row * 128 + c16 * 16;
        cp16(sB + swz(off), gB + (size_t)row * KTOT + k0 + c16 * 8);
    }
}

__global__ void __launch_bounds__(512, 1)
lstm_gemm_fused_kernel(const float* __restrict__ c_old,
                       const float* __restrict__ bf,
                       const float* __restrict__ bi,
                       const float* __restrict__ bo,
                       const float* __restrict__ bg,
                       float* __restrict__ out) {
    extern __shared__ __align__(1024) char smem[];
    const uint32_t sbase = smem_u32(smem);

    const int t    = threadIdx.x;
    const int lane = t & 31;
    const int wid  = t >> 5;      // 0..15
    const int wm   = wid & 3;     // warp m band: 64 rows
    const int wn   = wid >> 2;    // warp n band: 32 packed cols

    const int bid = blockIdx.x;
    const int mt = bid & 15;
    const int nt = bid >> 4;
    const int m0 = mt * BM;
    const int p0 = nt * BN;       // packed col base
    const int j0 = nt * 32;       // j base

    const __half* gA = g_Th + (size_t)m0 * KTOT;
    const __half* gB = g_Wh + (size_t)p0 * KTOT;

    float acc[4][4][4];
#pragma unroll
    for (int i = 0; i < 4; i++)
#pragma unroll
        for (int j = 0; j < 4; j++)
#pragma unroll
            for (int q = 0; q < 4; q++) acc[i][j][q] = 0.0f;

    stage_slab(sbase, sbase + A_STAGE_B, gA, gB, 0, t);
    asm volatile("cp.async.commit_group;" ::: "memory");
    stage_slab(sbase + STAGE_B, sbase + STAGE_B + A_STAGE_B, gA, gB, BK, t);
    asm volatile("cp.async.commit_group;" ::: "memory");

    const int lrow = lane & 15;
    const int lkof = (lane & 16) ? 8 : 0;

    const int NIT = KTOT / BK;     // 64
    for (int it = 0; it < NIT; it++) {
        asm volatile("cp.async.wait_group 1;" ::: "memory");
        __syncthreads();

        if (it + 2 < NIT) {
            int sn = (it + 2) % STG;
            stage_slab(sbase + sn * STAGE_B, sbase + sn * STAGE_B + A_STAGE_B,
                       gA, gB, (it + 2) * BK, t);
            asm volatile("cp.async.commit_group;" ::: "memory");
        }

        const int s = it % STG;
        const uint32_t aA = sbase + s * STAGE_B;
        const uint32_t aB = aA + A_STAGE_B;

#pragma unroll
        for (int kk = 0; kk < 4; kk++) {
            uint32_t a[4][4];
#pragma unroll
            for (int mf = 0; mf < 4; mf++) {
                uint32_t off = (uint32_t)(wm * 64 + mf * 16 + lrow) * 128
                             + (uint32_t)(kk * 16 + lkof) * 2;
                ldsm4(a[mf][0], a[mf][1], a[mf][2], a[mf][3], aA + swz(off));
            }
#pragma unroll
            for (int nf = 0; nf < 2; nf++) {
                uint32_t off = (uint32_t)(wn * 32 + nf * 16 + lrow) * 128
                             + (uint32_t)(kk * 16 + lkof) * 2;
                uint32_t b0, b1, b2, b3;
                ldsm4(b0, b1, b2, b3, aB + swz(off));
#pragma unroll
                for (int mf = 0; mf < 4; mf++) {
                    mma16816(acc[mf][nf * 2],     a[mf][0], a[mf][1], a[mf][2], a[mf][3], b0, b2);
                    mma16816(acc[mf][nf * 2 + 1], a[mf][0], a[mf][1], a[mf][2], a[mf][3], b1, b3);
                }
            }
        }
    }

    // ---- drain pipeline, then reuse smem as fp32 Z tile [256][EPI_PITCH] ----
    asm volatile("cp.async.wait_group 0;" ::: "memory");
    __syncthreads();

    float* zt = reinterpret_cast<float*>(smem);
    {
        const int r0 = wm * 64 + (lane >> 2);
        const int c0 = wn * 32 + (lane & 3) * 2;
#pragma unroll
        for (int mf = 0; mf < 4; mf++) {
            int row = r0 + mf * 16;
#pragma unroll
            for (int ci = 0; ci < 4; ci++) {
                int pc = c0 + (ci >> 1) * 16 + (ci & 1) * 8;
                *reinterpret_cast<float2*>(&zt[(size_t)row * EPI_PITCH + pc]) =
                    make_float2(acc[mf][ci][0], acc[mf][ci][1]);
                *reinterpret_cast<float2*>(&zt[(size_t)(row + 8) * EPI_PITCH + pc]) =
                    make_float2(acc[mf][ci][2], acc[mf][ci][3]);
            }
        }
    }
    __syncthreads();

    // ---- fused LSTM epilogue: thread = (warp -> m block, lane -> j) ----
    {
        const int j = lane;                  // 0..31
        const int jg = j0 + j;
        const float bfs = bf[jg];
        const float bis = bi[jg];
        const float bos = bo[jg];
        const float bgs = bg[jg];
        const int wb = t >> 5;               // 0..15
#pragma unroll
        for (int i = 0; i < 16; i++) {
            int ml = wb * 16 + i;
            float4 z = *reinterpret_cast<const float4*>(&zt[(size_t)ml * EPI_PITCH + j * 4]);
            float zf = z.x + bfs;
            float zi = z.y + bis;
            float zo = z.z + bos;
            float zg = z.w + bgs;
            int m = m0 + ml;
            float co = c_old[(size_t)m * NOUT + jg];
            float f  = sigmoidf_(zf);
            float ii = sigmoidf_(zi);
            float oo = sigmoidf_(zo);
            float g  = tanhf(zg);
            float c  = f * co + ii * g;
            float hh = oo * tanhf(c);
            out[(size_t)m * NOUT + jg] = c;
            out[(size_t)B_ * NOUT + (size_t)m * NOUT + jg] = hh;
        }
    }
}

// ---------------------------------------------------------------------------
// kernel_launch
// Input order: c_old, h_old, x, Wf, bf, Wi, bi, Wo, bo, Wg, bg, mode
// ---------------------------------------------------------------------------
extern "C" void kernel_launch(void* const* d_in, const int* in_sizes, int n_in,
                              void* d_out, int out_size) {
    const float* c_old = (const float*)d_in[0];
    const float* h_old = (const float*)d_in[1];
    const float* x     = (const float*)d_in[2];
    const float* Wf    = (const float*)d_in[3];
    const float* bf    = (const float*)d_in[4];
    const float* Wi    = (const float*)d_in[5];
    const float* bi    = (const float*)d_in[6];
    const float* Wo    = (const float*)d_in[7];
    const float* bo    = (const float*)d_in[8];
    const float* Wg    = (const float*)d_in[9];
    const float* bg    = (const float*)d_in[10];
    float* out = (float*)d_out;

    static int configured = 0;
    if (!configured) {
        cudaFuncSetAttribute(lstm_gemm_fused_kernel,
                             cudaFuncAttributeMaxDynamicSharedMemorySize, SMEM_TOTAL);
        configured = 1;
    }

    conv_T_kernel<<<(B_ * 512) / 256, 256>>>(x, h_old);
    conv_W_kernel<<<(NTOT * 512) / 256, 256>>>(Wf, Wi, Wo, Wg);

    lstm_gemm_fused_kernel<<<(B_ / BM) * (NTOT / BN), 512, SMEM_TOTAL>>>(
        c_old, bf, bi, bo, bg, out);
}